// round 7
// baseline (speedup 1.0000x reference)
#include <cuda_runtime.h>

// newIF spiking neuron forward (T=8), memory-bound streaming kernel.
// R7 probe: per-warp burst depth 16 — each thread owns TWO float4 groups
// (j and j + n4/2), all 16 LDG.128 front-batched before compute.
// Evidence: DRAM% tracks front-batch depth (4->71.7%, 8->77.4%), not occupancy.

#define T_STEPS 8

__global__ __launch_bounds__(256) void newif_kernel(
    const float4* __restrict__ x,
    const float*  __restrict__ thresh,
    float4*       __restrict__ out,
    int n4,    // neurons per timestep / 4
    int n4h)   // n4 / 2
{
    int j = blockIdx.x * blockDim.x + threadIdx.x;
    if (j >= n4h) return;

    const float thre = __ldg(thresh);
    const float half = 0.5f * thre;
    const float tcap = (float)T_STEPS * thre;

    // 16 independent front-batched LDG.E.128 (two coalesced streams)
    float4 xa[T_STEPS], xb[T_STEPS];
    #pragma unroll
    for (int t = 0; t < T_STEPS; t++) xa[t] = x[t * n4 + j];
    #pragma unroll
    for (int t = 0; t < T_STEPS; t++) xb[t] = x[t * n4 + j + n4h];

    float mema[4] = {half, half, half, half};
    float memb[4] = {half, half, half, half};
    float cnta[4] = {0.f, 0.f, 0.f, 0.f};
    float cntb[4] = {0.f, 0.f, 0.f, 0.f};
    unsigned ma[4] = {0u, 0u, 0u, 0u};
    unsigned mb[4] = {0u, 0u, 0u, 0u};

    #pragma unroll
    for (int t = 0; t < T_STEPS; t++) {
        const float* pa = reinterpret_cast<const float*>(&xa[t]);
        const float* pb = reinterpret_cast<const float*>(&xb[t]);
        #pragma unroll
        for (int l = 0; l < 4; l++) {
            float m = mema[l] + pa[l];
            if (m >= thre) { m -= thre; cnta[l] += 1.f; ma[l] |= (1u << t); }
            mema[l] = m;
            float n = memb[l] + pb[l];
            if (n >= thre) { n -= thre; cntb[l] += 1.f; mb[l] |= (1u << t); }
            memb[l] = n;
        }
    }

    float nta[4], ntb[4];
    #pragma unroll
    for (int l = 0; l < 4; l++) {
        float ca = mema[l] - half + cnta[l] * thre;
        float va = fminf(ca, tcap);
        nta[l] = ((va > 0.f) && (cnta[l] > 0.f)) ? (va / cnta[l]) : 0.f;
        float cb = memb[l] - half + cntb[l] * thre;
        float vb = fminf(cb, tcap);
        ntb[l] = ((vb > 0.f) && (cntb[l] > 0.f)) ? (vb / cntb[l]) : 0.f;
    }

    #pragma unroll
    for (int t = 0; t < T_STEPS; t++) {
        float4 oa, ob;
        oa.x = (ma[0] >> t & 1u) ? nta[0] : 0.f;
        oa.y = (ma[1] >> t & 1u) ? nta[1] : 0.f;
        oa.z = (ma[2] >> t & 1u) ? nta[2] : 0.f;
        oa.w = (ma[3] >> t & 1u) ? nta[3] : 0.f;
        ob.x = (mb[0] >> t & 1u) ? ntb[0] : 0.f;
        ob.y = (mb[1] >> t & 1u) ? ntb[1] : 0.f;
        ob.z = (mb[2] >> t & 1u) ? ntb[2] : 0.f;
        ob.w = (mb[3] >> t & 1u) ? ntb[3] : 0.f;
        __stcs(&out[t * n4 + j], oa);
        __stcs(&out[t * n4 + j + n4h], ob);
    }
}

extern "C" void kernel_launch(void* const* d_in, const int* in_sizes, int n_in,
                              void* d_out, int out_size) {
    const float* x      = (const float*)d_in[0];
    const float* thresh = (const float*)d_in[1];
    float* out          = (float*)d_out;

    int total = in_sizes[0];          // T * B * C * H * W
    int n_per_t = total / T_STEPS;    // B * C * H * W
    int n4 = n_per_t / 4;             // float4 units per timestep
    int n4h = n4 / 2;

    int threads = 256;
    int blocks = (n4h + threads - 1) / threads;
    newif_kernel<<<blocks, threads>>>(
        (const float4*)x, thresh, (float4*)out, n4, n4h);
}

// round 8
// speedup vs baseline: 1.0440x; 1.0440x over previous
#include <cuda_runtime.h>

// newIF spiking neuron forward (T=8) — converged roofline kernel.
// One thread = 4 neurons (float4). 8 front-batched independent LDG.E.128
// (measured optimum burst depth), 256-thread blocks, plain cache policy.
// 512MB mandatory traffic @ ~6.2TB/s achieved = HBM3e mixed-R/W ceiling.
// Swept and rejected: depth 4/16, 512t blocks, grid-stride, ldcs/ldcg/stcs,
// occupancy-first packing — all neutral or regressions (see round journal).

#define T_STEPS 8

__global__ __launch_bounds__(256) void newif_kernel(
    const float4* __restrict__ x,
    const float*  __restrict__ thresh,
    float4*       __restrict__ out,
    int n4)  // neurons per timestep / 4
{
    int i = blockIdx.x * blockDim.x + threadIdx.x;
    if (i >= n4) return;

    const float thre  = __ldg(thresh);
    const float half  = 0.5f * thre;
    const float tcap  = (float)T_STEPS * thre;

    // Front-batched loads: 8 independent LDG.E.128 (MLP=8 per thread)
    float4 xv[T_STEPS];
    #pragma unroll
    for (int t = 0; t < T_STEPS; t++)
        xv[t] = x[t * n4 + i];

    float mem[4] = {half, half, half, half};
    float cnt[4] = {0.f, 0.f, 0.f, 0.f};
    unsigned smask[4] = {0u, 0u, 0u, 0u};

    #pragma unroll
    for (int t = 0; t < T_STEPS; t++) {
        const float* xt = reinterpret_cast<const float*>(&xv[t]);
        #pragma unroll
        for (int l = 0; l < 4; l++) {
            float m = mem[l] + xt[l];
            bool s = (m >= thre);
            if (s) { m -= thre; cnt[l] += 1.f; smask[l] |= (1u << t); }
            mem[l] = m;
        }
    }

    float nt[4];
    #pragma unroll
    for (int l = 0; l < 4; l++) {
        float compen = mem[l] - half + cnt[l] * thre;
        float cv = fminf(compen, tcap);
        bool cond = (cv > 0.f) && (cnt[l] > 0.f);
        nt[l] = cond ? (cv / cnt[l]) : 0.f;
    }

    #pragma unroll
    for (int t = 0; t < T_STEPS; t++) {
        float4 o;
        o.x = (smask[0] >> t & 1u) ? nt[0] : 0.f;
        o.y = (smask[1] >> t & 1u) ? nt[1] : 0.f;
        o.z = (smask[2] >> t & 1u) ? nt[2] : 0.f;
        o.w = (smask[3] >> t & 1u) ? nt[3] : 0.f;
        out[t * n4 + i] = o;
    }
}

extern "C" void kernel_launch(void* const* d_in, const int* in_sizes, int n_in,
                              void* d_out, int out_size) {
    const float* x      = (const float*)d_in[0];
    const float* thresh = (const float*)d_in[1];
    float* out          = (float*)d_out;

    int total = in_sizes[0];          // T * B * C * H * W
    int n_per_t = total / T_STEPS;    // B * C * H * W
    int n4 = n_per_t / 4;             // float4 units per timestep

    int threads = 256;
    int blocks = (n4 + threads - 1) / threads;
    newif_kernel<<<blocks, threads>>>(
        (const float4*)x, thresh, (float4*)out, n4);
}

// round 9
// speedup vs baseline: 1.0550x; 1.0105x over previous
#include <cuda_runtime.h>

// newIF spiking neuron forward (T=8) — roofline kernel, final tuning probe.
// One thread = 4 neurons (float4), 8 front-batched independent LDG.E.128
// (measured optimum burst depth). R9: 128-thread blocks (finer scheduling
// granularity / smoother tail wave) + streaming hints (best-measured combo).
// 512MB mandatory traffic @ ~6.2TB/s achieved = HBM3e mixed-R/W ceiling.

#define T_STEPS 8

__global__ __launch_bounds__(128) void newif_kernel(
    const float4* __restrict__ x,
    const float*  __restrict__ thresh,
    float4*       __restrict__ out,
    int n4)  // neurons per timestep / 4
{
    int i = blockIdx.x * blockDim.x + threadIdx.x;
    if (i >= n4) return;

    const float thre  = __ldg(thresh);
    const float half  = 0.5f * thre;
    const float tcap  = (float)T_STEPS * thre;

    // Front-batched loads: 8 independent LDG.E.128 (MLP=8 per thread)
    float4 xv[T_STEPS];
    #pragma unroll
    for (int t = 0; t < T_STEPS; t++)
        xv[t] = __ldcs(&x[t * n4 + i]);

    float mem[4] = {half, half, half, half};
    float cnt[4] = {0.f, 0.f, 0.f, 0.f};
    unsigned smask[4] = {0u, 0u, 0u, 0u};

    #pragma unroll
    for (int t = 0; t < T_STEPS; t++) {
        const float* xt = reinterpret_cast<const float*>(&xv[t]);
        #pragma unroll
        for (int l = 0; l < 4; l++) {
            float m = mem[l] + xt[l];
            bool s = (m >= thre);
            if (s) { m -= thre; cnt[l] += 1.f; smask[l] |= (1u << t); }
            mem[l] = m;
        }
    }

    float nt[4];
    #pragma unroll
    for (int l = 0; l < 4; l++) {
        float compen = mem[l] - half + cnt[l] * thre;
        float cv = fminf(compen, tcap);
        bool cond = (cv > 0.f) && (cnt[l] > 0.f);
        nt[l] = cond ? (cv / cnt[l]) : 0.f;
    }

    #pragma unroll
    for (int t = 0; t < T_STEPS; t++) {
        float4 o;
        o.x = (smask[0] >> t & 1u) ? nt[0] : 0.f;
        o.y = (smask[1] >> t & 1u) ? nt[1] : 0.f;
        o.z = (smask[2] >> t & 1u) ? nt[2] : 0.f;
        o.w = (smask[3] >> t & 1u) ? nt[3] : 0.f;
        __stcs(&out[t * n4 + i], o);
    }
}

extern "C" void kernel_launch(void* const* d_in, const int* in_sizes, int n_in,
                              void* d_out, int out_size) {
    const float* x      = (const float*)d_in[0];
    const float* thresh = (const float*)d_in[1];
    float* out          = (float*)d_out;

    int total = in_sizes[0];          // T * B * C * H * W
    int n_per_t = total / T_STEPS;    // B * C * H * W
    int n4 = n_per_t / 4;             // float4 units per timestep

    int threads = 128;
    int blocks = (n4 + threads - 1) / threads;
    newif_kernel<<<blocks, threads>>>(
        (const float4*)x, thresh, (float4*)out, n4);
}